// round 15
// baseline (speedup 1.0000x reference)
#include <cuda_runtime.h>
#include <cuda_bf16.h>
#include <math.h>
#include <stdint.h>

#define NN 32
#define DD 512
#define PP 3136
#define KK 64
#define PSPLIT 7
#define PCHUNK 448   // PP / PSPLIT = 14 * 32 exactly
#define NTILE 25     // ceil(PP/128)

// Scratch (static device globals — no allocation)
__device__ __align__(16) __nv_bfloat16 g_wbf[KK * DD];               // 64 KB
__device__ __align__(16) __nv_bfloat16 g_soft[(size_t)NN * KK * PP]; // a*rn, 12.8 MB
__device__ __align__(16) __nv_bfloat16 g_aggp[(size_t)PSPLIT * NN * KK * DD]; // bf16, 14.7 MB
__device__ float g_asumt[NN * KK * NTILE];                           // 200 KB
__device__ float g_nsq[NN * KK];                                     // per-row ||v̂||²

// ---------------------------------------------------------------------------
__device__ __forceinline__ uint32_t pack_bf2(float lo, float hi) {
    uint32_t r;
    asm("cvt.rn.bf16x2.f32 %0, %1, %2;" : "=r"(r) : "f"(hi), "f"(lo));
    return r;
}
__device__ __forceinline__ void ldm_x4(uint32_t r[4], uint32_t addr) {
    asm volatile("ldmatrix.sync.aligned.m8n8.x4.shared.b16 {%0,%1,%2,%3}, [%4];"
                 : "=r"(r[0]), "=r"(r[1]), "=r"(r[2]), "=r"(r[3]) : "r"(addr));
}
__device__ __forceinline__ void ldm_x4t(uint32_t r[4], uint32_t addr) {
    asm volatile("ldmatrix.sync.aligned.m8n8.x4.trans.shared.b16 {%0,%1,%2,%3}, [%4];"
                 : "=r"(r[0]), "=r"(r[1]), "=r"(r[2]), "=r"(r[3]) : "r"(addr));
}
__device__ __forceinline__ void mma_bf16(float c[4], const uint32_t a[4],
                                         uint32_t b0, uint32_t b1) {
    asm volatile("mma.sync.aligned.m16n8k16.row.col.f32.bf16.bf16.f32 "
                 "{%0,%1,%2,%3}, {%4,%5,%6,%7}, {%8,%9}, {%0,%1,%2,%3};"
                 : "+f"(c[0]), "+f"(c[1]), "+f"(c[2]), "+f"(c[3])
                 : "r"(a[0]), "r"(a[1]), "r"(a[2]), "r"(a[3]), "r"(b0), "r"(b1));
}
__device__ __forceinline__ void cp_async16(uint32_t saddr, const void* g) {
    asm volatile("cp.async.ca.shared.global [%0], [%1], 16;" :: "r"(saddr), "l"(g));
}
#define CP_COMMIT() asm volatile("cp.async.commit_group;")
#define CP_WAIT0()  asm volatile("cp.async.wait_group 0;")

// ---------------------------------------------------------------------------
// 1) convert W to bf16 (row-major [k][d])
// ---------------------------------------------------------------------------
__global__ void __launch_bounds__(256) k_wbf(const float* __restrict__ w) {
    int i = blockIdx.x * 256 + threadIdx.x;
    if (i >= KK * DD / 2) return;
    ((uint32_t*)g_wbf)[i] = pack_bf2(w[2 * i], w[2 * i + 1]);
}

// ---------------------------------------------------------------------------
// 2) fused: per-pixel L2 norm + logits GEMM + softmax — 256 threads (8 warps).
//    Warp w owns pixel m-block w (16 pixels), all 8 k n-blocks.
// ---------------------------------------------------------------------------
__global__ void __launch_bounds__(256) k_logits_softmax(const float* __restrict__ x) {
    const int bx = blockIdx.x;
    const int n  = blockIdx.y;
    const int p0 = bx * 128;
    const int tid  = threadIdx.x;
    const int warp = tid >> 5;
    const int lane = tid & 31;
    const int gq   = lane >> 2;
    const int tig  = lane & 3;

    __shared__ __align__(16) uint16_t x_s[2][32 * 136];   // [d][p] pitch 136 (272B)
    __shared__ __align__(16) uint16_t w_s[2][64 * 40];    // [k][d] pitch 40 (80B)
    __shared__ float rn[128];
    __shared__ float sred[8][64];
    __shared__ float sqs[16][128];

    const int valid = (PP - p0 < 128) ? (PP - p0) : 128;   // 128 or 64

    float acc[8][4];
#pragma unroll
    for (int nb = 0; nb < 8; ++nb)
#pragma unroll
        for (int r = 0; r < 4; ++r) acc[nb][r] = 0.f;

    float sq[8];
#pragma unroll
    for (int i = 0; i < 8; ++i) sq[i] = 0.f;

    const float* xn = x + (size_t)n * DD * PP;
    float4 vx[2][2];   // 2 tasks x 8 pixels; oct = tid&15 fixed

#define LDG_X(d0)                                                               \
    {                                                                           \
        _Pragma("unroll")                                                       \
        for (int t4 = 0; t4 < 2; ++t4) {                                        \
            int e = t4 * 256 + tid, row = e >> 4, oct = e & 15;                 \
            if (oct * 8 < valid) {                                              \
                const float* s = xn + (size_t)((d0) + row) * PP + p0 + oct * 8; \
                vx[t4][0] = *(const float4*)s;                                  \
                vx[t4][1] = *(const float4*)(s + 4);                            \
            } else {                                                            \
                vx[t4][0] = make_float4(0.f, 0.f, 0.f, 0.f);                    \
                vx[t4][1] = make_float4(0.f, 0.f, 0.f, 0.f);                    \
            }                                                                   \
        }                                                                       \
    }

#define STS_X(buf)                                                              \
    {                                                                           \
        _Pragma("unroll")                                                       \
        for (int t4 = 0; t4 < 2; ++t4) {                                        \
            int e = t4 * 256 + tid, row = e >> 4, oct = e & 15;                 \
            sq[0] = fmaf(vx[t4][0].x, vx[t4][0].x, sq[0]);                      \
            sq[1] = fmaf(vx[t4][0].y, vx[t4][0].y, sq[1]);                      \
            sq[2] = fmaf(vx[t4][0].z, vx[t4][0].z, sq[2]);                      \
            sq[3] = fmaf(vx[t4][0].w, vx[t4][0].w, sq[3]);                      \
            sq[4] = fmaf(vx[t4][1].x, vx[t4][1].x, sq[4]);                      \
            sq[5] = fmaf(vx[t4][1].y, vx[t4][1].y, sq[5]);                      \
            sq[6] = fmaf(vx[t4][1].z, vx[t4][1].z, sq[6]);                      \
            sq[7] = fmaf(vx[t4][1].w, vx[t4][1].w, sq[7]);                      \
            uint4 o;                                                            \
            o.x = pack_bf2(vx[t4][0].x, vx[t4][0].y);                           \
            o.y = pack_bf2(vx[t4][0].z, vx[t4][0].w);                           \
            o.z = pack_bf2(vx[t4][1].x, vx[t4][1].y);                           \
            o.w = pack_bf2(vx[t4][1].z, vx[t4][1].w);                           \
            *(uint4*)&x_s[buf][row * 136 + oct * 8] = o;                        \
        }                                                                       \
    }

#define CPA_W(d0, buf)                                                          \
    {                                                                           \
        int row = tid >> 2, c = tid & 3;                                        \
        cp_async16((uint32_t)__cvta_generic_to_shared(                          \
                       &w_s[buf][row * 40 + c * 8]),                            \
                   g_wbf + row * DD + (d0) + c * 8);                            \
    }

    CPA_W(0, 0);
    CP_COMMIT();
    LDG_X(0);
    STS_X(0);
    CP_WAIT0();
    __syncthreads();

    for (int ch = 0; ch < 16; ++ch) {
        int buf = ch & 1;
        if (ch < 15) {
            LDG_X((ch + 1) * 32);
            CPA_W((ch + 1) * 32, buf ^ 1);
            CP_COMMIT();
        }
#pragma unroll
        for (int s = 0; s < 2; ++s) {
            uint32_t afr[4];
            {
                int row  = s * 16 + (lane & 7) + ((lane >> 4) & 1) * 8;
                int pcol = warp * 16 + ((lane >> 3) & 1) * 8;
                ldm_x4t(afr, (uint32_t)__cvta_generic_to_shared(
                                 &x_s[buf][row * 136 + pcol]));
            }
#pragma unroll
            for (int qb = 0; qb < 4; ++qb) {
                int row = qb * 16 + (lane & 7) + ((lane >> 3) & 1) * 8;
                uint32_t bfr[4];
                ldm_x4(bfr, (uint32_t)__cvta_generic_to_shared(
                                &w_s[buf][row * 40 + s * 16 + ((lane >> 4) & 1) * 8]));
                mma_bf16(acc[2 * qb],     afr, bfr[0], bfr[2]);
                mma_bf16(acc[2 * qb + 1], afr, bfr[1], bfr[3]);
            }
        }
        if (ch < 15) {
            STS_X(buf ^ 1);
            CP_WAIT0();
        }
        __syncthreads();
    }

    // reduce ||x||² across the 16 threads sharing each pixel-oct, compute rn
#pragma unroll
    for (int i = 0; i < 8; ++i)
        sqs[tid >> 4][(tid & 15) * 8 + i] = sq[i];
    __syncthreads();
    if (tid < 128) {
        float s = 0.f;
#pragma unroll
        for (int j = 0; j < 16; ++j) s += sqs[j][tid];
        rn[tid] = 1.f / fmaxf(sqrtf(s), 1e-12f);
    }
    __syncthreads();

    // softmax over K per pixel, in registers; logits scaled by rn here.
#pragma unroll
    for (int half = 0; half < 2; ++half) {
        int pl = warp * 16 + half * 8 + gq;
        int p = p0 + pl;
        float rnv = rn[pl];
        float mx = -1e30f;
#pragma unroll
        for (int nb = 0; nb < 8; ++nb) {
            float l0 = acc[nb][half * 2] * rnv;
            float l1 = acc[nb][half * 2 + 1] * rnv;
            acc[nb][half * 2] = l0;
            acc[nb][half * 2 + 1] = l1;
            mx = fmaxf(mx, fmaxf(l0, l1));
        }
        mx = fmaxf(mx, __shfl_xor_sync(0xffffffff, mx, 1));
        mx = fmaxf(mx, __shfl_xor_sync(0xffffffff, mx, 2));
        float ssum = 0.f;
#pragma unroll
        for (int nb = 0; nb < 8; ++nb) {
            float e0 = __expf(acc[nb][half * 2] - mx);
            float e1 = __expf(acc[nb][half * 2 + 1] - mx);
            acc[nb][half * 2] = e0;
            acc[nb][half * 2 + 1] = e1;
            ssum += e0 + e1;
        }
        ssum += __shfl_xor_sync(0xffffffff, ssum, 1);
        ssum += __shfl_xor_sync(0xffffffff, ssum, 2);
        float inv = (p < PP) ? 1.f / ssum : 0.f;
        __nv_bfloat16* op = g_soft + (size_t)n * KK * PP + p;
#pragma unroll
        for (int nb = 0; nb < 8; ++nb) {
            float a0 = acc[nb][half * 2] * inv;
            float a1 = acc[nb][half * 2 + 1] * inv;
            acc[nb][half * 2] = a0;
            acc[nb][half * 2 + 1] = a1;
            if (p < PP) {
                op[(size_t)(nb * 8 + 2 * tig) * PP]     = __float2bfloat16_rn(a0 * rnv);
                op[(size_t)(nb * 8 + 2 * tig + 1) * PP] = __float2bfloat16_rn(a1 * rnv);
            }
        }
    }

    // per-tile a_sum per k (fp32): warp sums its 16 pixels, then combine 8 warps
    float skE[8], skO[8];
#pragma unroll
    for (int nb = 0; nb < 8; ++nb) {
        skE[nb] = acc[nb][0] + acc[nb][2];
        skO[nb] = acc[nb][1] + acc[nb][3];
    }
#pragma unroll
    for (int mask = 4; mask <= 16; mask <<= 1)
#pragma unroll
        for (int nb = 0; nb < 8; ++nb) {
            skE[nb] += __shfl_xor_sync(0xffffffff, skE[nb], mask);
            skO[nb] += __shfl_xor_sync(0xffffffff, skO[nb], mask);
        }
    if (lane < 4) {
#pragma unroll
        for (int nb = 0; nb < 8; ++nb) {
            sred[warp][nb * 8 + 2 * lane]     = skE[nb];
            sred[warp][nb * 8 + 2 * lane + 1] = skO[nb];
        }
    }
    __syncthreads();
    if (tid < KK) {
        float s = 0.f;
#pragma unroll
        for (int w = 0; w < 8; ++w) s += sred[w][tid];
        g_asumt[(n * KK + tid) * NTILE + bx] = s;
    }
#undef LDG_X
#undef STS_X
#undef CPA_W
}

// ---------------------------------------------------------------------------
// 3) agg GEMM — 256 threads (8 warps); warp (kh = w>>2, wd = w&3).
//    (byte-identical to R14 — validated)
// ---------------------------------------------------------------------------
__global__ void __launch_bounds__(256) k_agg(const float* __restrict__ x) {
    const int d0 = blockIdx.x * 128;
    const int n  = blockIdx.y;
    const int ps = blockIdx.z;
    const int tid  = threadIdx.x;
    const int warp = tid >> 5;
    const int lane = tid & 31;
    const int kh   = warp >> 2;
    const int wd   = warp & 3;

    __shared__ __align__(16) uint16_t a_s[2][64 * 40];
    __shared__ __align__(16) uint16_t x_s[2][128 * 40];

    float acc[2][4][4];
#pragma unroll
    for (int mb = 0; mb < 2; ++mb)
#pragma unroll
        for (int nb = 0; nb < 4; ++nb)
#pragma unroll
            for (int r = 0; r < 4; ++r) acc[mb][nb][r] = 0.f;

    const float* xn = x + (size_t)n * DD * PP;
    const __nv_bfloat16* an = g_soft + (size_t)n * KK * PP;
    const int pbeg = ps * PCHUNK;

    float4 vx[2][2];

#define LDG_XA(pc0)                                                             \
    {                                                                           \
        _Pragma("unroll")                                                       \
        for (int t4 = 0; t4 < 2; ++t4) {                                        \
            int e = t4 * 256 + tid, row = e >> 2, oct = e & 3;                  \
            const float* s = xn + (size_t)(d0 + row) * PP + (pc0) + oct * 8;    \
            vx[t4][0] = *(const float4*)s;                                      \
            vx[t4][1] = *(const float4*)(s + 4);                                \
        }                                                                       \
    }

#define STS_XA(buf)                                                             \
    {                                                                           \
        _Pragma("unroll")                                                       \
        for (int t4 = 0; t4 < 2; ++t4) {                                        \
            int e = t4 * 256 + tid, row = e >> 2, oct = e & 3;                  \
            uint4 o;                                                            \
            o.x = pack_bf2(vx[t4][0].x, vx[t4][0].y);                           \
            o.y = pack_bf2(vx[t4][0].z, vx[t4][0].w);                           \
            o.z = pack_bf2(vx[t4][1].x, vx[t4][1].y);                           \
            o.w = pack_bf2(vx[t4][1].z, vx[t4][1].w);                           \
            *(uint4*)&x_s[buf][row * 40 + oct * 8] = o;                         \
        }                                                                       \
    }

#define CPA_A(pc0, buf)                                                         \
    {                                                                           \
        int row = tid >> 2, c = tid & 3;                                        \
        cp_async16((uint32_t)__cvta_generic_to_shared(                          \
                       &a_s[buf][row * 40 + c * 8]),                            \
                   an + (size_t)row * PP + (pc0) + c * 8);                      \
    }

    CPA_A(pbeg, 0);
    CP_COMMIT();
    LDG_XA(pbeg);
    STS_XA(0);
    CP_WAIT0();
    __syncthreads();

    const int NCH = PCHUNK / 32;   // 14
    for (int ch = 0; ch < NCH; ++ch) {
        int buf = ch & 1;
        if (ch < NCH - 1) {
            LDG_XA(pbeg + (ch + 1) * 32);
            CPA_A(pbeg + (ch + 1) * 32, buf ^ 1);
            CP_COMMIT();
        }
#pragma unroll
        for (int s = 0; s < 2; ++s) {
            int rbase = (lane & 7) + ((lane >> 3) & 1) * 8;
            int cofs  = s * 16 + ((lane >> 4) & 1) * 8;
            uint32_t afr[2][4];
#pragma unroll
            for (int mb = 0; mb < 2; ++mb) {
                uint32_t ad = (uint32_t)__cvta_generic_to_shared(
                    &a_s[buf][(kh * 32 + mb * 16 + rbase) * 40 + cofs]);
                ldm_x4(afr[mb], ad);
            }
#pragma unroll
            for (int nq = 0; nq < 2; ++nq) {
                uint32_t bd = (uint32_t)__cvta_generic_to_shared(
                    &x_s[buf][(wd * 32 + nq * 16 + rbase) * 40 + cofs]);
                uint32_t bfr[4];
                ldm_x4(bfr, bd);
#pragma unroll
                for (int mb = 0; mb < 2; ++mb) {
                    mma_bf16(acc[mb][2 * nq],     afr[mb], bfr[0], bfr[2]);
                    mma_bf16(acc[mb][2 * nq + 1], afr[mb], bfr[1], bfr[3]);
                }
            }
        }
        if (ch < NCH - 1) {
            STS_XA(buf ^ 1);
            CP_WAIT0();
        }
        __syncthreads();
    }

    __nv_bfloat16* op = g_aggp + ((size_t)(ps * NN + n) * KK + kh * 32) * DD
                      + d0 + wd * 32;
    int r = lane >> 2, cq = (lane & 3) * 2;
#pragma unroll
    for (int mb = 0; mb < 2; ++mb)
#pragma unroll
        for (int nb = 0; nb < 4; ++nb) {
            int d = nb * 8 + cq;
            *(uint32_t*)&op[(size_t)(mb * 16 + r) * DD + d] =
                pack_bf2(acc[mb][nb][0], acc[mb][nb][1]);
            *(uint32_t*)&op[(size_t)(mb * 16 + r + 8) * DD + d] =
                pack_bf2(acc[mb][nb][2], acc[mb][nb][3]);
        }
#undef LDG_XA
#undef STS_XA
#undef CPA_A
}

// ---------------------------------------------------------------------------
// 4) vlad: a_sum + (Σ bf16 partials − a_sum·c) + intra L2 norm
// ---------------------------------------------------------------------------
__global__ void __launch_bounds__(128) k_vlad(const float* __restrict__ centroids,
                                              float* __restrict__ out) {
    const int k = blockIdx.x;
    const int n = blockIdx.y;
    const int tid = threadIdx.x;
    __shared__ float red[128];

    float asum = 0.f;
    const float* at = g_asumt + (n * KK + k) * NTILE;
#pragma unroll
    for (int t = 0; t < NTILE; ++t) asum += at[t];

    float a0 = 0.f, a1 = 0.f, a2 = 0.f, a3 = 0.f;
#pragma unroll
    for (int ps = 0; ps < PSPLIT; ++ps) {
        uint2 v = *(const uint2*)(g_aggp +
            (((size_t)ps * NN + n) * KK + k) * DD + tid * 4);
        float2 lo = __bfloat1622float2(*(__nv_bfloat162*)&v.x);
        float2 hi = __bfloat1622float2(*(__nv_bfloat162*)&v.y);
        a0 += lo.x; a1 += lo.y; a2 += hi.x; a3 += hi.y;
    }
    float4 c = *(const float4*)(centroids + k * DD + tid * 4);
    float4 v;
    v.x = a0 - asum * c.x;
    v.y = a1 - asum * c.y;
    v.z = a2 - asum * c.z;
    v.w = a3 - asum * c.w;
    float ss = v.x * v.x + v.y * v.y + v.z * v.z + v.w * v.w;

    red[tid] = ss;
    __syncthreads();
    for (int w = 64; w > 0; w >>= 1) {
        if (tid < w) red[tid] += red[tid + w];
        __syncthreads();
    }
    float sst  = red[0];
    float rinv = 1.f / fmaxf(sqrtf(sst), 1e-12f);
    if (tid == 0) g_nsq[n * KK + k] = sst * rinv * rinv;

    float4 o;
    o.x = v.x * rinv; o.y = v.y * rinv; o.z = v.z * rinv; o.w = v.w * rinv;
    *(float4*)(out + ((size_t)n * KK + k) * DD + tid * 4) = o;
}

// ---------------------------------------------------------------------------
// 5) global L2 norm per n — 8 blocks per image
// ---------------------------------------------------------------------------
__global__ void __launch_bounds__(256) k_gnorm(float* __restrict__ out) {
    const int n  = blockIdx.y;
    const int sl = blockIdx.x;    // 0..7
    const int tid = threadIdx.x;
    __shared__ float red[64];
    __shared__ float rinv_s;
    if (tid < 64) red[tid] = g_nsq[n * KK + tid];
    __syncthreads();
    if (tid < 32) {
        float s = red[tid] + red[tid + 32];
#pragma unroll
        for (int m = 16; m > 0; m >>= 1)
            s += __shfl_xor_sync(0xffffffff, s, m);
        if (tid == 0) rinv_s = 1.f / fmaxf(sqrtf(s), 1e-12f);
    }
    __syncthreads();
    float rinv = rinv_s;
    float4* row = (float4*)(out + (size_t)n * KK * DD) + sl * 1024 + tid;
#pragma unroll
    for (int i = 0; i < 4; ++i) {
        float4 v = row[i * 256];
        v.x *= rinv; v.y *= rinv; v.z *= rinv; v.w *= rinv;
        row[i * 256] = v;
    }
}

// ---------------------------------------------------------------------------
extern "C" void kernel_launch(void* const* d_in, const int* in_sizes, int n_in,
                              void* d_out, int out_size) {
    const float* x = (const float*)d_in[0];        // (32, 512, 56, 56)
    const float* w = (const float*)d_in[1];        // (64, 512)
    const float* c = (const float*)d_in[2];        // (64, 512)
    float* out = (float*)d_out;                    // (32, 32768) fp32

    k_wbf<<<(KK * DD / 2 + 255) / 256, 256>>>(w);

    dim3 gB(NTILE, NN);                            // 25 x 32
    k_logits_softmax<<<gB, 256>>>(x);

    dim3 gC(DD / 128, NN, PSPLIT);                 // 4 x 32 x 7 = 896 CTAs
    k_agg<<<gC, 256>>>(x);

    dim3 gD(KK, NN);                               // 64 x 32
    k_vlad<<<gD, 128>>>(c, out);

    dim3 gG(8, NN);                                // 8 x 32
    k_gnorm<<<gG, 256>>>(out);
}

// round 16
// speedup vs baseline: 1.0440x; 1.0440x over previous
#include <cuda_runtime.h>
#include <cuda_bf16.h>
#include <math.h>
#include <stdint.h>

#define NN 32
#define DD 512
#define PP 3136
#define KK 64
#define PSPLIT 7
#define PCHUNK 448   // PP / PSPLIT = 14 * 32 exactly
#define NTILE 25     // ceil(PP/128)

// Scratch (static device globals — no allocation)
__device__ __align__(16) __nv_bfloat16 g_wbf[KK * DD];               // 64 KB
__device__ __align__(16) __nv_bfloat16 g_soft[(size_t)NN * KK * PP]; // a*rn, 12.8 MB
__device__ __align__(16) __nv_bfloat16 g_aggp[(size_t)PSPLIT * NN * KK * DD]; // bf16, 14.7 MB
__device__ float g_asumt[NN * KK * NTILE];                           // 200 KB
__device__ float g_nsq[NN * KK];                                     // per-row ||v̂||²

// logits dynamic smem layout (bytes); uint16 elements unless noted
#define LSM_XS    0          // x_s [2][64*136] bf16 = 34816 B
#define LSM_WS    34816      // w_s [2][64*72]  bf16 = 18432 B
#define LSM_RN    53248      // rn [128] f32 = 512 B
#define LSM_SRED  53760      // sred [4][64] f32 = 1024 B
#define LSM_SQS   54784      // sqs [8][128] f32 = 4096 B
#define LSM_TOTAL 58880

// ---------------------------------------------------------------------------
__device__ __forceinline__ uint32_t pack_bf2(float lo, float hi) {
    uint32_t r;
    asm("cvt.rn.bf16x2.f32 %0, %1, %2;" : "=r"(r) : "f"(hi), "f"(lo));
    return r;
}
__device__ __forceinline__ void ldm_x4(uint32_t r[4], uint32_t addr) {
    asm volatile("ldmatrix.sync.aligned.m8n8.x4.shared.b16 {%0,%1,%2,%3}, [%4];"
                 : "=r"(r[0]), "=r"(r[1]), "=r"(r[2]), "=r"(r[3]) : "r"(addr));
}
__device__ __forceinline__ void ldm_x4t(uint32_t r[4], uint32_t addr) {
    asm volatile("ldmatrix.sync.aligned.m8n8.x4.trans.shared.b16 {%0,%1,%2,%3}, [%4];"
                 : "=r"(r[0]), "=r"(r[1]), "=r"(r[2]), "=r"(r[3]) : "r"(addr));
}
__device__ __forceinline__ void mma_bf16(float c[4], const uint32_t a[4],
                                         uint32_t b0, uint32_t b1) {
    asm volatile("mma.sync.aligned.m16n8k16.row.col.f32.bf16.bf16.f32 "
                 "{%0,%1,%2,%3}, {%4,%5,%6,%7}, {%8,%9}, {%0,%1,%2,%3};"
                 : "+f"(c[0]), "+f"(c[1]), "+f"(c[2]), "+f"(c[3])
                 : "r"(a[0]), "r"(a[1]), "r"(a[2]), "r"(a[3]), "r"(b0), "r"(b1));
}
__device__ __forceinline__ void cp_async16(uint32_t saddr, const void* g) {
    asm volatile("cp.async.ca.shared.global [%0], [%1], 16;" :: "r"(saddr), "l"(g));
}
#define CP_COMMIT() asm volatile("cp.async.commit_group;")
#define CP_WAIT0()  asm volatile("cp.async.wait_group 0;")

// ---------------------------------------------------------------------------
// 1) convert W to bf16 (row-major [k][d])
// ---------------------------------------------------------------------------
__global__ void __launch_bounds__(256) k_wbf(const float* __restrict__ w) {
    int i = blockIdx.x * 256 + threadIdx.x;
    if (i >= KK * DD / 2) return;
    ((uint32_t*)g_wbf)[i] = pack_bf2(w[2 * i], w[2 * i + 1]);
}

// ---------------------------------------------------------------------------
// 2) fused: per-pixel L2 norm + logits GEMM + softmax. 128 threads (R14
//    layout) but 64-d chunks: 8 mainloop iterations instead of 16.
// ---------------------------------------------------------------------------
__global__ void __launch_bounds__(128) k_logits_softmax(const float* __restrict__ x) {
    extern __shared__ __align__(16) uint8_t lsm[];
    uint16_t* x_s  = (uint16_t*)(lsm + LSM_XS);    // [2][64*136]
    uint16_t* w_s  = (uint16_t*)(lsm + LSM_WS);    // [2][64*72]
    float*    rn   = (float*)(lsm + LSM_RN);       // [128]
    float*    sred = (float*)(lsm + LSM_SRED);     // [4][64]
    float*    sqs  = (float*)(lsm + LSM_SQS);      // [8][128]

    const int bx = blockIdx.x;
    const int n  = blockIdx.y;
    const int p0 = bx * 128;
    const int tid  = threadIdx.x;
    const int warp = tid >> 5;
    const int lane = tid & 31;
    const int gq   = lane >> 2;
    const int tig  = lane & 3;

    const int valid = (PP - p0 < 128) ? (PP - p0) : 128;   // 128 or 64

    float acc[2][8][4];
#pragma unroll
    for (int mb = 0; mb < 2; ++mb)
#pragma unroll
        for (int nb = 0; nb < 8; ++nb)
#pragma unroll
            for (int r = 0; r < 4; ++r) acc[mb][nb][r] = 0.f;

    float sq[8];
#pragma unroll
    for (int i = 0; i < 8; ++i) sq[i] = 0.f;

    const float* xn = x + (size_t)n * DD * PP;
    float4 vx[4][2];   // one 32-row sub-batch at a time

// load 32 d-rows starting at global d = (dg): 512 float4-tasks, 4/thread
#define LDG_X(dg)                                                               \
    {                                                                           \
        _Pragma("unroll")                                                       \
        for (int t4 = 0; t4 < 4; ++t4) {                                        \
            int e = t4 * 128 + tid, row = e >> 4, oct = e & 15;                 \
            if (oct * 8 < valid) {                                              \
                const float* s = xn + (size_t)((dg) + row) * PP + p0 + oct * 8; \
                vx[t4][0] = *(const float4*)s;                                  \
                vx[t4][1] = *(const float4*)(s + 4);                            \
            } else {                                                            \
                vx[t4][0] = make_float4(0.f, 0.f, 0.f, 0.f);                    \
                vx[t4][1] = make_float4(0.f, 0.f, 0.f, 0.f);                    \
            }                                                                   \
        }                                                                       \
    }

// store the sub-batch into buffer rows [sub .. sub+32)
#define STS_X(buf, sub)                                                         \
    {                                                                           \
        _Pragma("unroll")                                                       \
        for (int t4 = 0; t4 < 4; ++t4) {                                        \
            int e = t4 * 128 + tid, row = e >> 4, oct = e & 15;                 \
            sq[0] = fmaf(vx[t4][0].x, vx[t4][0].x, sq[0]);                      \
            sq[1] = fmaf(vx[t4][0].y, vx[t4][0].y, sq[1]);                      \
            sq[2] = fmaf(vx[t4][0].z, vx[t4][0].z, sq[2]);                      \
            sq[3] = fmaf(vx[t4][0].w, vx[t4][0].w, sq[3]);                      \
            sq[4] = fmaf(vx[t4][1].x, vx[t4][1].x, sq[4]);                      \
            sq[5] = fmaf(vx[t4][1].y, vx[t4][1].y, sq[5]);                      \
            sq[6] = fmaf(vx[t4][1].z, vx[t4][1].z, sq[6]);                      \
            sq[7] = fmaf(vx[t4][1].w, vx[t4][1].w, sq[7]);                      \
            uint4 o;                                                            \
            o.x = pack_bf2(vx[t4][0].x, vx[t4][0].y);                           \
            o.y = pack_bf2(vx[t4][0].z, vx[t4][0].w);                           \
            o.z = pack_bf2(vx[t4][1].x, vx[t4][1].y);                           \
            o.w = pack_bf2(vx[t4][1].z, vx[t4][1].w);                           \
            *(uint4*)&x_s[(buf) * 8704 + ((sub) + row) * 136 + oct * 8] = o;    \
        }                                                                       \
    }

// W chunk: 64 k-rows x 64 d -> 512 cp16 tasks, 4/thread, pitch 72
#define CPA_W(dg, buf)                                                          \
    {                                                                           \
        _Pragma("unroll")                                                       \
        for (int t = 0; t < 4; ++t) {                                           \
            int e = t * 128 + tid, row = e >> 3, c = e & 7;                     \
            cp_async16((uint32_t)__cvta_generic_to_shared(                      \
                           &w_s[(buf) * 4608 + row * 72 + c * 8]),              \
                       g_wbf + row * DD + (dg) + c * 8);                        \
        }                                                                       \
    }

    CPA_W(0, 0);
    CP_COMMIT();
    LDG_X(0);
    STS_X(0, 0);
    LDG_X(32);
    STS_X(0, 32);
    CP_WAIT0();
    __syncthreads();

    for (int ch = 0; ch < 8; ++ch) {
        int buf = ch & 1;
        if (ch < 7) {
            LDG_X((ch + 1) * 64);            // sub0 in flight over compute
            CPA_W((ch + 1) * 64, buf ^ 1);
            CP_COMMIT();
        }
#pragma unroll
        for (int s = 0; s < 4; ++s) {
            uint32_t afr[2][4];
#pragma unroll
            for (int mb = 0; mb < 2; ++mb) {
                int row  = s * 16 + (lane & 7) + ((lane >> 4) & 1) * 8;
                int pcol = (warp * 2 + mb) * 16 + ((lane >> 3) & 1) * 8;
                ldm_x4t(afr[mb], (uint32_t)__cvta_generic_to_shared(
                                     &x_s[buf * 8704 + row * 136 + pcol]));
            }
#pragma unroll
            for (int qb = 0; qb < 4; ++qb) {
                int row = qb * 16 + (lane & 7) + ((lane >> 3) & 1) * 8;
                uint32_t bfr[4];
                ldm_x4(bfr, (uint32_t)__cvta_generic_to_shared(
                                &w_s[buf * 4608 + row * 72 + s * 16 +
                                     ((lane >> 4) & 1) * 8]));
#pragma unroll
                for (int mb = 0; mb < 2; ++mb) {
                    mma_bf16(acc[mb][2 * qb],     afr[mb], bfr[0], bfr[2]);
                    mma_bf16(acc[mb][2 * qb + 1], afr[mb], bfr[1], bfr[3]);
                }
            }
        }
        if (ch < 7) {
            STS_X(buf ^ 1, 0);
            LDG_X((ch + 1) * 64 + 32);
            STS_X(buf ^ 1, 32);
            CP_WAIT0();
        }
        __syncthreads();
    }

    // reduce ||x||² across the 8 threads sharing each pixel-oct, compute rn
#pragma unroll
    for (int i = 0; i < 8; ++i)
        sqs[(tid >> 4) * 128 + (tid & 15) * 8 + i] = sq[i];
    __syncthreads();
    {
        float s = 0.f;
#pragma unroll
        for (int j = 0; j < 8; ++j) s += sqs[j * 128 + tid];
        rn[tid] = 1.f / fmaxf(sqrtf(s), 1e-12f);
    }
    __syncthreads();

    // softmax over K per pixel, in registers; logits scaled by rn here.
#pragma unroll
    for (int mb = 0; mb < 2; ++mb) {
#pragma unroll
        for (int half = 0; half < 2; ++half) {
            int pl = warp * 32 + mb * 16 + half * 8 + gq;
            int p = p0 + pl;
            float rnv = rn[pl];
            float mx = -1e30f;
#pragma unroll
            for (int nb = 0; nb < 8; ++nb) {
                float l0 = acc[mb][nb][half * 2] * rnv;
                float l1 = acc[mb][nb][half * 2 + 1] * rnv;
                acc[mb][nb][half * 2] = l0;
                acc[mb][nb][half * 2 + 1] = l1;
                mx = fmaxf(mx, fmaxf(l0, l1));
            }
            mx = fmaxf(mx, __shfl_xor_sync(0xffffffff, mx, 1));
            mx = fmaxf(mx, __shfl_xor_sync(0xffffffff, mx, 2));
            float ssum = 0.f;
#pragma unroll
            for (int nb = 0; nb < 8; ++nb) {
                float e0 = __expf(acc[mb][nb][half * 2] - mx);
                float e1 = __expf(acc[mb][nb][half * 2 + 1] - mx);
                acc[mb][nb][half * 2] = e0;
                acc[mb][nb][half * 2 + 1] = e1;
                ssum += e0 + e1;
            }
            ssum += __shfl_xor_sync(0xffffffff, ssum, 1);
            ssum += __shfl_xor_sync(0xffffffff, ssum, 2);
            float inv = (p < PP) ? 1.f / ssum : 0.f;
            __nv_bfloat16* op = g_soft + (size_t)n * KK * PP + p;
#pragma unroll
            for (int nb = 0; nb < 8; ++nb) {
                float a0 = acc[mb][nb][half * 2] * inv;
                float a1 = acc[mb][nb][half * 2 + 1] * inv;
                acc[mb][nb][half * 2] = a0;
                acc[mb][nb][half * 2 + 1] = a1;
                if (p < PP) {
                    op[(size_t)(nb * 8 + 2 * tig) * PP]     = __float2bfloat16_rn(a0 * rnv);
                    op[(size_t)(nb * 8 + 2 * tig + 1) * PP] = __float2bfloat16_rn(a1 * rnv);
                }
            }
        }
    }

    // per-tile a_sum per k (fp32)
    float skE[8], skO[8];
#pragma unroll
    for (int nb = 0; nb < 8; ++nb) {
        skE[nb] = acc[0][nb][0] + acc[0][nb][2] + acc[1][nb][0] + acc[1][nb][2];
        skO[nb] = acc[0][nb][1] + acc[0][nb][3] + acc[1][nb][1] + acc[1][nb][3];
    }
#pragma unroll
    for (int mask = 4; mask <= 16; mask <<= 1)
#pragma unroll
        for (int nb = 0; nb < 8; ++nb) {
            skE[nb] += __shfl_xor_sync(0xffffffff, skE[nb], mask);
            skO[nb] += __shfl_xor_sync(0xffffffff, skO[nb], mask);
        }
    if (lane < 4) {
#pragma unroll
        for (int nb = 0; nb < 8; ++nb) {
            sred[warp * 64 + nb * 8 + 2 * lane]     = skE[nb];
            sred[warp * 64 + nb * 8 + 2 * lane + 1] = skO[nb];
        }
    }
    __syncthreads();
    if (tid < KK)
        g_asumt[(n * KK + tid) * NTILE + bx] =
            sred[0 * 64 + tid] + sred[1 * 64 + tid] +
            sred[2 * 64 + tid] + sred[3 * 64 + tid];
#undef LDG_X
#undef STS_X
#undef CPA_W
}

// ---------------------------------------------------------------------------
// 3) agg GEMM — 256 threads (8 warps); warp (kh = w>>2, wd = w&3).
//    (byte-identical to R14 — validated best)
// ---------------------------------------------------------------------------
__global__ void __launch_bounds__(256) k_agg(const float* __restrict__ x) {
    const int d0 = blockIdx.x * 128;
    const int n  = blockIdx.y;
    const int ps = blockIdx.z;
    const int tid  = threadIdx.x;
    const int warp = tid >> 5;
    const int lane = tid & 31;
    const int kh   = warp >> 2;
    const int wd   = warp & 3;

    __shared__ __align__(16) uint16_t a_s[2][64 * 40];
    __shared__ __align__(16) uint16_t x_s[2][128 * 40];

    float acc[2][4][4];
#pragma unroll
    for (int mb = 0; mb < 2; ++mb)
#pragma unroll
        for (int nb = 0; nb < 4; ++nb)
#pragma unroll
            for (int r = 0; r < 4; ++r) acc[mb][nb][r] = 0.f;

    const float* xn = x + (size_t)n * DD * PP;
    const __nv_bfloat16* an = g_soft + (size_t)n * KK * PP;
    const int pbeg = ps * PCHUNK;

    float4 vx[2][2];

#define LDG_XA(pc0)                                                             \
    {                                                                           \
        _Pragma("unroll")                                                       \
        for (int t4 = 0; t4 < 2; ++t4) {                                        \
            int e = t4 * 256 + tid, row = e >> 2, oct = e & 3;                  \
            const float* s = xn + (size_t)(d0 + row) * PP + (pc0) + oct * 8;    \
            vx[t4][0] = *(const float4*)s;                                      \
            vx[t4][1] = *(const float4*)(s + 4);                                \
        }                                                                       \
    }

#define STS_XA(buf)                                                             \
    {                                                                           \
        _Pragma("unroll")                                                       \
        for (int t4 = 0; t4 < 2; ++t4) {                                        \
            int e = t4 * 256 + tid, row = e >> 2, oct = e & 3;                  \
            uint4 o;                                                            \
            o.x = pack_bf2(vx[t4][0].x, vx[t4][0].y);                           \
            o.y = pack_bf2(vx[t4][0].z, vx[t4][0].w);                           \
            o.z = pack_bf2(vx[t4][1].x, vx[t4][1].y);                           \
            o.w = pack_bf2(vx[t4][1].z, vx[t4][1].w);                           \
            *(uint4*)&x_s[buf][row * 40 + oct * 8] = o;                         \
        }                                                                       \
    }

#define CPA_A(pc0, buf)                                                         \
    {                                                                           \
        int row = tid >> 2, c = tid & 3;                                        \
        cp_async16((uint32_t)__cvta_generic_to_shared(                          \
                       &a_s[buf][row * 40 + c * 8]),                            \
                   an + (size_t)row * PP + (pc0) + c * 8);                      \
    }

    CPA_A(pbeg, 0);
    CP_COMMIT();
    LDG_XA(pbeg);
    STS_XA(0);
    CP_WAIT0();
    __syncthreads();

    const int NCH = PCHUNK / 32;   // 14
    for (int ch = 0; ch < NCH; ++ch) {
        int buf = ch & 1;
        if (ch < NCH - 1) {
            LDG_XA(pbeg + (ch + 1) * 32);
            CPA_A(pbeg + (ch + 1) * 32, buf ^ 1);
            CP_COMMIT();
        }
#pragma unroll
        for (int s = 0; s < 2; ++s) {
            int rbase = (lane & 7) + ((lane >> 3) & 1) * 8;
            int cofs  = s * 16 + ((lane >> 4) & 1) * 8;
            uint32_t afr[2][4];
#pragma unroll
            for (int mb = 0; mb < 2; ++mb) {
                uint32_t ad = (uint32_t)__cvta_generic_to_shared(
                    &a_s[buf][(kh * 32 + mb * 16 + rbase) * 40 + cofs]);
                ldm_x4(afr[mb], ad);
            }
#pragma unroll
            for (int nq = 0; nq < 2; ++nq) {
                uint32_t bd = (uint32_t)__cvta_generic_to_shared(
                    &x_s[buf][(wd * 32 + nq * 16 + rbase) * 40 + cofs]);
                uint32_t bfr[4];
                ldm_x4(bfr, bd);
#pragma unroll
                for (int mb = 0; mb < 2; ++mb) {
                    mma_bf16(acc[mb][2 * nq],     afr[mb], bfr[0], bfr[2]);
                    mma_bf16(acc[mb][2 * nq + 1], afr[mb], bfr[1], bfr[3]);
                }
            }
        }
        if (ch < NCH - 1) {
            STS_XA(buf ^ 1);
            CP_WAIT0();
        }
        __syncthreads();
    }

    __nv_bfloat16* op = g_aggp + ((size_t)(ps * NN + n) * KK + kh * 32) * DD
                      + d0 + wd * 32;
    int r = lane >> 2, cq = (lane & 3) * 2;
#pragma unroll
    for (int mb = 0; mb < 2; ++mb)
#pragma unroll
        for (int nb = 0; nb < 4; ++nb) {
            int d = nb * 8 + cq;
            *(uint32_t*)&op[(size_t)(mb * 16 + r) * DD + d] =
                pack_bf2(acc[mb][nb][0], acc[mb][nb][1]);
            *(uint32_t*)&op[(size_t)(mb * 16 + r + 8) * DD + d] =
                pack_bf2(acc[mb][nb][2], acc[mb][nb][3]);
        }
#undef LDG_XA
#undef STS_XA
#undef CPA_A
}

// ---------------------------------------------------------------------------
// 4) vlad: a_sum + (Σ bf16 partials − a_sum·c) + intra L2 norm
// ---------------------------------------------------------------------------
__global__ void __launch_bounds__(128) k_vlad(const float* __restrict__ centroids,
                                              float* __restrict__ out) {
    const int k = blockIdx.x;
    const int n = blockIdx.y;
    const int tid = threadIdx.x;
    __shared__ float red[128];

    float asum = 0.f;
    const float* at = g_asumt + (n * KK + k) * NTILE;
#pragma unroll
    for (int t = 0; t < NTILE; ++t) asum += at[t];

    float a0 = 0.f, a1 = 0.f, a2 = 0.f, a3 = 0.f;
#pragma unroll
    for (int ps = 0; ps < PSPLIT; ++ps) {
        uint2 v = *(const uint2*)(g_aggp +
            (((size_t)ps * NN + n) * KK + k) * DD + tid * 4);
        float2 lo = __bfloat1622float2(*(__nv_bfloat162*)&v.x);
        float2 hi = __bfloat1622float2(*(__nv_bfloat162*)&v.y);
        a0 += lo.x; a1 += lo.y; a2 += hi.x; a3 += hi.y;
    }
    float4 c = *(const float4*)(centroids + k * DD + tid * 4);
    float4 v;
    v.x = a0 - asum * c.x;
    v.y = a1 - asum * c.y;
    v.z = a2 - asum * c.z;
    v.w = a3 - asum * c.w;
    float ss = v.x * v.x + v.y * v.y + v.z * v.z + v.w * v.w;

    red[tid] = ss;
    __syncthreads();
    for (int w = 64; w > 0; w >>= 1) {
        if (tid < w) red[tid] += red[tid + w];
        __syncthreads();
    }
    float sst  = red[0];
    float rinv = 1.f / fmaxf(sqrtf(sst), 1e-12f);
    if (tid == 0) g_nsq[n * KK + k] = sst * rinv * rinv;

    float4 o;
    o.x = v.x * rinv; o.y = v.y * rinv; o.z = v.z * rinv; o.w = v.w * rinv;
    *(float4*)(out + ((size_t)n * KK + k) * DD + tid * 4) = o;
}

// ---------------------------------------------------------------------------
// 5) global L2 norm per n — 8 blocks per image
// ---------------------------------------------------------------------------
__global__ void __launch_bounds__(256) k_gnorm(float* __restrict__ out) {
    const int n  = blockIdx.y;
    const int sl = blockIdx.x;    // 0..7
    const int tid = threadIdx.x;
    __shared__ float red[64];
    __shared__ float rinv_s;
    if (tid < 64) red[tid] = g_nsq[n * KK + tid];
    __syncthreads();
    if (tid < 32) {
        float s = red[tid] + red[tid + 32];
#pragma unroll
        for (int m = 16; m > 0; m >>= 1)
            s += __shfl_xor_sync(0xffffffff, s, m);
        if (tid == 0) rinv_s = 1.f / fmaxf(sqrtf(s), 1e-12f);
    }
    __syncthreads();
    float rinv = rinv_s;
    float4* row = (float4*)(out + (size_t)n * KK * DD) + sl * 1024 + tid;
#pragma unroll
    for (int i = 0; i < 4; ++i) {
        float4 v = row[i * 256];
        v.x *= rinv; v.y *= rinv; v.z *= rinv; v.w *= rinv;
        row[i * 256] = v;
    }
}

// ---------------------------------------------------------------------------
extern "C" void kernel_launch(void* const* d_in, const int* in_sizes, int n_in,
                              void* d_out, int out_size) {
    const float* x = (const float*)d_in[0];        // (32, 512, 56, 56)
    const float* w = (const float*)d_in[1];        // (64, 512)
    const float* c = (const float*)d_in[2];        // (64, 512)
    float* out = (float*)d_out;                    // (32, 32768) fp32

    cudaFuncSetAttribute(k_logits_softmax,
                         cudaFuncAttributeMaxDynamicSharedMemorySize, LSM_TOTAL);

    k_wbf<<<(KK * DD / 2 + 255) / 256, 256>>>(w);

    dim3 gB(NTILE, NN);                            // 25 x 32
    k_logits_softmax<<<gB, 128, LSM_TOTAL>>>(x);

    dim3 gC(DD / 128, NN, PSPLIT);                 // 4 x 32 x 7 = 896 CTAs
    k_agg<<<gC, 256>>>(x);

    dim3 gD(KK, NN);                               // 64 x 32
    k_vlad<<<gD, 128>>>(c, out);

    dim3 gG(8, NN);                                // 8 x 32
    k_gnorm<<<gG, 256>>>(out);
}

// round 17
// speedup vs baseline: 1.0761x; 1.0307x over previous
#include <cuda_runtime.h>
#include <cuda_bf16.h>
#include <math.h>
#include <stdint.h>

#define NN 32
#define DD 512
#define PP 3136
#define KK 64
#define PSPLIT 7
#define PCHUNK 448   // PP / PSPLIT = 7 * 64 exactly
#define NTILE 25     // ceil(PP/128)

// Scratch (static device globals — no allocation)
__device__ __align__(16) __nv_bfloat16 g_wbf[KK * DD];               // 64 KB
__device__ __align__(16) __nv_bfloat16 g_soft[(size_t)NN * KK * PP]; // a*rn, 12.8 MB
__device__ __align__(16) __nv_bfloat16 g_aggp[(size_t)PSPLIT * NN * KK * DD]; // bf16, 14.7 MB
__device__ float g_asumt[NN * KK * NTILE];                           // 200 KB
__device__ float g_nsq[NN * KK];                                     // per-row ||v̂||²

// logits dynamic smem layout (bytes)
#define LSM_XS    0          // x_s [2][64*136] bf16 = 34816 B
#define LSM_WS    34816      // w_s [2][64*72]  bf16 = 18432 B
#define LSM_RN    53248      // rn [128] f32 = 512 B
#define LSM_SRED  53760      // sred [4][64] f32 = 1024 B
#define LSM_SQS   54784      // sqs [8][128] f32 = 4096 B
#define LSM_TOTAL 58880

// agg dynamic smem: x_s [2][128*72] + a_s [2][64*72] bf16
#define ASM_XCNT  (2 * 128 * 72)     // uint16 count
#define ASM_ACNT  (2 * 64 * 72)
#define ASM_TOTAL ((ASM_XCNT + ASM_ACNT) * 2)   // 55296 B

// ---------------------------------------------------------------------------
__device__ __forceinline__ uint32_t pack_bf2(float lo, float hi) {
    uint32_t r;
    asm("cvt.rn.bf16x2.f32 %0, %1, %2;" : "=r"(r) : "f"(hi), "f"(lo));
    return r;
}
__device__ __forceinline__ void ldm_x4(uint32_t r[4], uint32_t addr) {
    asm volatile("ldmatrix.sync.aligned.m8n8.x4.shared.b16 {%0,%1,%2,%3}, [%4];"
                 : "=r"(r[0]), "=r"(r[1]), "=r"(r[2]), "=r"(r[3]) : "r"(addr));
}
__device__ __forceinline__ void ldm_x4t(uint32_t r[4], uint32_t addr) {
    asm volatile("ldmatrix.sync.aligned.m8n8.x4.trans.shared.b16 {%0,%1,%2,%3}, [%4];"
                 : "=r"(r[0]), "=r"(r[1]), "=r"(r[2]), "=r"(r[3]) : "r"(addr));
}
__device__ __forceinline__ void mma_bf16(float c[4], const uint32_t a[4],
                                         uint32_t b0, uint32_t b1) {
    asm volatile("mma.sync.aligned.m16n8k16.row.col.f32.bf16.bf16.f32 "
                 "{%0,%1,%2,%3}, {%4,%5,%6,%7}, {%8,%9}, {%0,%1,%2,%3};"
                 : "+f"(c[0]), "+f"(c[1]), "+f"(c[2]), "+f"(c[3])
                 : "r"(a[0]), "r"(a[1]), "r"(a[2]), "r"(a[3]), "r"(b0), "r"(b1));
}
__device__ __forceinline__ void cp_async16(uint32_t saddr, const void* g) {
    asm volatile("cp.async.ca.shared.global [%0], [%1], 16;" :: "r"(saddr), "l"(g));
}
#define CP_COMMIT() asm volatile("cp.async.commit_group;")
#define CP_WAIT0()  asm volatile("cp.async.wait_group 0;")

// ---------------------------------------------------------------------------
// 1) convert W to bf16 (row-major [k][d])
// ---------------------------------------------------------------------------
__global__ void __launch_bounds__(256) k_wbf(const float* __restrict__ w) {
    int i = blockIdx.x * 256 + threadIdx.x;
    if (i >= KK * DD / 2) return;
    ((uint32_t*)g_wbf)[i] = pack_bf2(w[2 * i], w[2 * i + 1]);
}

// ---------------------------------------------------------------------------
// 2) fused: per-pixel L2 norm + logits GEMM + softmax. 128 threads,
//    64-d chunks (8 mainloop iterations). (byte-identical to R16 — best)
// ---------------------------------------------------------------------------
__global__ void __launch_bounds__(128) k_logits_softmax(const float* __restrict__ x) {
    extern __shared__ __align__(16) uint8_t lsm[];
    uint16_t* x_s  = (uint16_t*)(lsm + LSM_XS);
    uint16_t* w_s  = (uint16_t*)(lsm + LSM_WS);
    float*    rn   = (float*)(lsm + LSM_RN);
    float*    sred = (float*)(lsm + LSM_SRED);
    float*    sqs  = (float*)(lsm + LSM_SQS);

    const int bx = blockIdx.x;
    const int n  = blockIdx.y;
    const int p0 = bx * 128;
    const int tid  = threadIdx.x;
    const int warp = tid >> 5;
    const int lane = tid & 31;
    const int gq   = lane >> 2;
    const int tig  = lane & 3;

    const int valid = (PP - p0 < 128) ? (PP - p0) : 128;

    float acc[2][8][4];
#pragma unroll
    for (int mb = 0; mb < 2; ++mb)
#pragma unroll
        for (int nb = 0; nb < 8; ++nb)
#pragma unroll
            for (int r = 0; r < 4; ++r) acc[mb][nb][r] = 0.f;

    float sq[8];
#pragma unroll
    for (int i = 0; i < 8; ++i) sq[i] = 0.f;

    const float* xn = x + (size_t)n * DD * PP;
    float4 vx[4][2];

#define LDG_X(dg)                                                               \
    {                                                                           \
        _Pragma("unroll")                                                       \
        for (int t4 = 0; t4 < 4; ++t4) {                                        \
            int e = t4 * 128 + tid, row = e >> 4, oct = e & 15;                 \
            if (oct * 8 < valid) {                                              \
                const float* s = xn + (size_t)((dg) + row) * PP + p0 + oct * 8; \
                vx[t4][0] = *(const float4*)s;                                  \
                vx[t4][1] = *(const float4*)(s + 4);                            \
            } else {                                                            \
                vx[t4][0] = make_float4(0.f, 0.f, 0.f, 0.f);                    \
                vx[t4][1] = make_float4(0.f, 0.f, 0.f, 0.f);                    \
            }                                                                   \
        }                                                                       \
    }

#define STS_X(buf, sub)                                                         \
    {                                                                           \
        _Pragma("unroll")                                                       \
        for (int t4 = 0; t4 < 4; ++t4) {                                        \
            int e = t4 * 128 + tid, row = e >> 4, oct = e & 15;                 \
            sq[0] = fmaf(vx[t4][0].x, vx[t4][0].x, sq[0]);                      \
            sq[1] = fmaf(vx[t4][0].y, vx[t4][0].y, sq[1]);                      \
            sq[2] = fmaf(vx[t4][0].z, vx[t4][0].z, sq[2]);                      \
            sq[3] = fmaf(vx[t4][0].w, vx[t4][0].w, sq[3]);                      \
            sq[4] = fmaf(vx[t4][1].x, vx[t4][1].x, sq[4]);                      \
            sq[5] = fmaf(vx[t4][1].y, vx[t4][1].y, sq[5]);                      \
            sq[6] = fmaf(vx[t4][1].z, vx[t4][1].z, sq[6]);                      \
            sq[7] = fmaf(vx[t4][1].w, vx[t4][1].w, sq[7]);                      \
            uint4 o;                                                            \
            o.x = pack_bf2(vx[t4][0].x, vx[t4][0].y);                           \
            o.y = pack_bf2(vx[t4][0].z, vx[t4][0].w);                           \
            o.z = pack_bf2(vx[t4][1].x, vx[t4][1].y);                           \
            o.w = pack_bf2(vx[t4][1].z, vx[t4][1].w);                           \
            *(uint4*)&x_s[(buf) * 8704 + ((sub) + row) * 136 + oct * 8] = o;    \
        }                                                                       \
    }

#define CPA_W(dg, buf)                                                          \
    {                                                                           \
        _Pragma("unroll")                                                       \
        for (int t = 0; t < 4; ++t) {                                           \
            int e = t * 128 + tid, row = e >> 3, c = e & 7;                     \
            cp_async16((uint32_t)__cvta_generic_to_shared(                      \
                           &w_s[(buf) * 4608 + row * 72 + c * 8]),              \
                       g_wbf + row * DD + (dg) + c * 8);                        \
        }                                                                       \
    }

    CPA_W(0, 0);
    CP_COMMIT();
    LDG_X(0);
    STS_X(0, 0);
    LDG_X(32);
    STS_X(0, 32);
    CP_WAIT0();
    __syncthreads();

    for (int ch = 0; ch < 8; ++ch) {
        int buf = ch & 1;
        if (ch < 7) {
            LDG_X((ch + 1) * 64);
            CPA_W((ch + 1) * 64, buf ^ 1);
            CP_COMMIT();
        }
#pragma unroll
        for (int s = 0; s < 4; ++s) {
            uint32_t afr[2][4];
#pragma unroll
            for (int mb = 0; mb < 2; ++mb) {
                int row  = s * 16 + (lane & 7) + ((lane >> 4) & 1) * 8;
                int pcol = (warp * 2 + mb) * 16 + ((lane >> 3) & 1) * 8;
                ldm_x4t(afr[mb], (uint32_t)__cvta_generic_to_shared(
                                     &x_s[buf * 8704 + row * 136 + pcol]));
            }
#pragma unroll
            for (int qb = 0; qb < 4; ++qb) {
                int row = qb * 16 + (lane & 7) + ((lane >> 3) & 1) * 8;
                uint32_t bfr[4];
                ldm_x4(bfr, (uint32_t)__cvta_generic_to_shared(
                                &w_s[buf * 4608 + row * 72 + s * 16 +
                                     ((lane >> 4) & 1) * 8]));
#pragma unroll
                for (int mb = 0; mb < 2; ++mb) {
                    mma_bf16(acc[mb][2 * qb],     afr[mb], bfr[0], bfr[2]);
                    mma_bf16(acc[mb][2 * qb + 1], afr[mb], bfr[1], bfr[3]);
                }
            }
        }
        if (ch < 7) {
            STS_X(buf ^ 1, 0);
            LDG_X((ch + 1) * 64 + 32);
            STS_X(buf ^ 1, 32);
            CP_WAIT0();
        }
        __syncthreads();
    }

#pragma unroll
    for (int i = 0; i < 8; ++i)
        sqs[(tid >> 4) * 128 + (tid & 15) * 8 + i] = sq[i];
    __syncthreads();
    {
        float s = 0.f;
#pragma unroll
        for (int j = 0; j < 8; ++j) s += sqs[j * 128 + tid];
        rn[tid] = 1.f / fmaxf(sqrtf(s), 1e-12f);
    }
    __syncthreads();

#pragma unroll
    for (int mb = 0; mb < 2; ++mb) {
#pragma unroll
        for (int half = 0; half < 2; ++half) {
            int pl = warp * 32 + mb * 16 + half * 8 + gq;
            int p = p0 + pl;
            float rnv = rn[pl];
            float mx = -1e30f;
#pragma unroll
            for (int nb = 0; nb < 8; ++nb) {
                float l0 = acc[mb][nb][half * 2] * rnv;
                float l1 = acc[mb][nb][half * 2 + 1] * rnv;
                acc[mb][nb][half * 2] = l0;
                acc[mb][nb][half * 2 + 1] = l1;
                mx = fmaxf(mx, fmaxf(l0, l1));
            }
            mx = fmaxf(mx, __shfl_xor_sync(0xffffffff, mx, 1));
            mx = fmaxf(mx, __shfl_xor_sync(0xffffffff, mx, 2));
            float ssum = 0.f;
#pragma unroll
            for (int nb = 0; nb < 8; ++nb) {
                float e0 = __expf(acc[mb][nb][half * 2] - mx);
                float e1 = __expf(acc[mb][nb][half * 2 + 1] - mx);
                acc[mb][nb][half * 2] = e0;
                acc[mb][nb][half * 2 + 1] = e1;
                ssum += e0 + e1;
            }
            ssum += __shfl_xor_sync(0xffffffff, ssum, 1);
            ssum += __shfl_xor_sync(0xffffffff, ssum, 2);
            float inv = (p < PP) ? 1.f / ssum : 0.f;
            __nv_bfloat16* op = g_soft + (size_t)n * KK * PP + p;
#pragma unroll
            for (int nb = 0; nb < 8; ++nb) {
                float a0 = acc[mb][nb][half * 2] * inv;
                float a1 = acc[mb][nb][half * 2 + 1] * inv;
                acc[mb][nb][half * 2] = a0;
                acc[mb][nb][half * 2 + 1] = a1;
                if (p < PP) {
                    op[(size_t)(nb * 8 + 2 * tig) * PP]     = __float2bfloat16_rn(a0 * rnv);
                    op[(size_t)(nb * 8 + 2 * tig + 1) * PP] = __float2bfloat16_rn(a1 * rnv);
                }
            }
        }
    }

    float skE[8], skO[8];
#pragma unroll
    for (int nb = 0; nb < 8; ++nb) {
        skE[nb] = acc[0][nb][0] + acc[0][nb][2] + acc[1][nb][0] + acc[1][nb][2];
        skO[nb] = acc[0][nb][1] + acc[0][nb][3] + acc[1][nb][1] + acc[1][nb][3];
    }
#pragma unroll
    for (int mask = 4; mask <= 16; mask <<= 1)
#pragma unroll
        for (int nb = 0; nb < 8; ++nb) {
            skE[nb] += __shfl_xor_sync(0xffffffff, skE[nb], mask);
            skO[nb] += __shfl_xor_sync(0xffffffff, skO[nb], mask);
        }
    if (lane < 4) {
#pragma unroll
        for (int nb = 0; nb < 8; ++nb) {
            sred[warp * 64 + nb * 8 + 2 * lane]     = skE[nb];
            sred[warp * 64 + nb * 8 + 2 * lane + 1] = skO[nb];
        }
    }
    __syncthreads();
    if (tid < KK)
        g_asumt[(n * KK + tid) * NTILE + bx] =
            sred[0 * 64 + tid] + sred[1 * 64 + tid] +
            sred[2 * 64 + tid] + sred[3 * 64 + tid];
#undef LDG_X
#undef STS_X
#undef CPA_W
}

// ---------------------------------------------------------------------------
// 3) agg GEMM — 256 threads, 64-p chunks (7 mainloop iterations).
//    Warp (kh = w>>2, wd = w&3). Dynamic smem 54 KB, pitch 72.
// ---------------------------------------------------------------------------
__global__ void __launch_bounds__(256) k_agg(const float* __restrict__ x) {
    extern __shared__ __align__(16) uint16_t asm_[];
    uint16_t* x_s = asm_;                 // [2][128*72]
    uint16_t* a_s = asm_ + ASM_XCNT;      // [2][64*72]

    const int d0 = blockIdx.x * 128;
    const int n  = blockIdx.y;
    const int ps = blockIdx.z;
    const int tid  = threadIdx.x;
    const int warp = tid >> 5;
    const int lane = tid & 31;
    const int kh   = warp >> 2;
    const int wd   = warp & 3;

    float acc[2][4][4];
#pragma unroll
    for (int mb = 0; mb < 2; ++mb)
#pragma unroll
        for (int nb = 0; nb < 4; ++nb)
#pragma unroll
            for (int r = 0; r < 4; ++r) acc[mb][nb][r] = 0.f;

    const float* xn = x + (size_t)n * DD * PP;
    const __nv_bfloat16* an = g_soft + (size_t)n * KK * PP;
    const int pbeg = ps * PCHUNK;

    float4 vx[4][2];   // x: 1024 tasks (128 rows x 8 octs), 4/thread

#define LDG_XA(pc0)                                                             \
    {                                                                           \
        _Pragma("unroll")                                                       \
        for (int t4 = 0; t4 < 4; ++t4) {                                        \
            int e = t4 * 256 + tid, row = e >> 3, oct = e & 7;                  \
            const float* s = xn + (size_t)(d0 + row) * PP + (pc0) + oct * 8;    \
            vx[t4][0] = *(const float4*)s;                                      \
            vx[t4][1] = *(const float4*)(s + 4);                                \
        }                                                                       \
    }

#define STS_XA(buf)                                                             \
    {                                                                           \
        _Pragma("unroll")                                                       \
        for (int t4 = 0; t4 < 4; ++t4) {                                        \
            int e = t4 * 256 + tid, row = e >> 3, oct = e & 7;                  \
            uint4 o;                                                            \
            o.x = pack_bf2(vx[t4][0].x, vx[t4][0].y);                           \
            o.y = pack_bf2(vx[t4][0].z, vx[t4][0].w);                           \
            o.z = pack_bf2(vx[t4][1].x, vx[t4][1].y);                           \
            o.w = pack_bf2(vx[t4][1].z, vx[t4][1].w);                           \
            *(uint4*)&x_s[(buf) * (128 * 72) + row * 72 + oct * 8] = o;         \
        }                                                                       \
    }

#define CPA_A(pc0, buf)                                                         \
    {                                                                           \
        _Pragma("unroll")                                                       \
        for (int t = 0; t < 2; ++t) {                                           \
            int e = t * 256 + tid, row = e >> 3, c = e & 7;                     \
            cp_async16((uint32_t)__cvta_generic_to_shared(                      \
                           &a_s[(buf) * (64 * 72) + row * 72 + c * 8]),         \
                       an + (size_t)row * PP + (pc0) + c * 8);                  \
        }                                                                       \
    }

    CPA_A(pbeg, 0);
    CP_COMMIT();
    LDG_XA(pbeg);
    STS_XA(0);
    CP_WAIT0();
    __syncthreads();

    const int NCH = PCHUNK / 64;   // 7
    for (int ch = 0; ch < NCH; ++ch) {
        int buf = ch & 1;
        if (ch < NCH - 1) {
            LDG_XA(pbeg + (ch + 1) * 64);
            CPA_A(pbeg + (ch + 1) * 64, buf ^ 1);
            CP_COMMIT();
        }
#pragma unroll
        for (int s = 0; s < 4; ++s) {
            int rbase = (lane & 7) + ((lane >> 3) & 1) * 8;
            int cofs  = s * 16 + ((lane >> 4) & 1) * 8;
            uint32_t afr[2][4];
#pragma unroll
            for (int mb = 0; mb < 2; ++mb)
                ldm_x4(afr[mb], (uint32_t)__cvta_generic_to_shared(
                    &a_s[buf * (64 * 72) + (kh * 32 + mb * 16 + rbase) * 72 + cofs]));
#pragma unroll
            for (int nq = 0; nq < 2; ++nq) {
                uint32_t bfr[4];
                ldm_x4(bfr, (uint32_t)__cvta_generic_to_shared(
                    &x_s[buf * (128 * 72) + (wd * 32 + nq * 16 + rbase) * 72 + cofs]));
#pragma unroll
                for (int mb = 0; mb < 2; ++mb) {
                    mma_bf16(acc[mb][2 * nq],     afr[mb], bfr[0], bfr[2]);
                    mma_bf16(acc[mb][2 * nq + 1], afr[mb], bfr[1], bfr[3]);
                }
            }
        }
        if (ch < NCH - 1) {
            STS_XA(buf ^ 1);
            CP_WAIT0();
        }
        __syncthreads();
    }

    __nv_bfloat16* op = g_aggp + ((size_t)(ps * NN + n) * KK + kh * 32) * DD
                      + d0 + wd * 32;
    int r = lane >> 2, cq = (lane & 3) * 2;
#pragma unroll
    for (int mb = 0; mb < 2; ++mb)
#pragma unroll
        for (int nb = 0; nb < 4; ++nb) {
            int d = nb * 8 + cq;
            *(uint32_t*)&op[(size_t)(mb * 16 + r) * DD + d] =
                pack_bf2(acc[mb][nb][0], acc[mb][nb][1]);
            *(uint32_t*)&op[(size_t)(mb * 16 + r + 8) * DD + d] =
                pack_bf2(acc[mb][nb][2], acc[mb][nb][3]);
        }
#undef LDG_XA
#undef STS_XA
#undef CPA_A
}

// ---------------------------------------------------------------------------
// 4) vlad: a_sum + (Σ bf16 partials − a_sum·c) + intra L2 norm.
//    Shuffle-tree reduction (1 barrier instead of 7).
// ---------------------------------------------------------------------------
__global__ void __launch_bounds__(128) k_vlad(const float* __restrict__ centroids,
                                              float* __restrict__ out) {
    const int k = blockIdx.x;
    const int n = blockIdx.y;
    const int tid = threadIdx.x;
    const int warp = tid >> 5;
    const int lane = tid & 31;
    __shared__ float red[4];

    float asum = 0.f;
    const float* at = g_asumt + (n * KK + k) * NTILE;
#pragma unroll
    for (int t = 0; t < NTILE; ++t) asum += at[t];

    float a0 = 0.f, a1 = 0.f, a2 = 0.f, a3 = 0.f;
#pragma unroll
    for (int ps = 0; ps < PSPLIT; ++ps) {
        uint2 v = *(const uint2*)(g_aggp +
            (((size_t)ps * NN + n) * KK + k) * DD + tid * 4);
        float2 lo = __bfloat1622float2(*(__nv_bfloat162*)&v.x);
        float2 hi = __bfloat1622float2(*(__nv_bfloat162*)&v.y);
        a0 += lo.x; a1 += lo.y; a2 += hi.x; a3 += hi.y;
    }
    float4 c = *(const float4*)(centroids + k * DD + tid * 4);
    float4 v;
    v.x = a0 - asum * c.x;
    v.y = a1 - asum * c.y;
    v.z = a2 - asum * c.z;
    v.w = a3 - asum * c.w;
    float ss = v.x * v.x + v.y * v.y + v.z * v.z + v.w * v.w;

#pragma unroll
    for (int m = 16; m > 0; m >>= 1)
        ss += __shfl_xor_sync(0xffffffff, ss, m);
    if (lane == 0) red[warp] = ss;
    __syncthreads();
    float sst  = red[0] + red[1] + red[2] + red[3];
    float rinv = 1.f / fmaxf(sqrtf(sst), 1e-12f);
    if (tid == 0) g_nsq[n * KK + k] = sst * rinv * rinv;

    float4 o;
    o.x = v.x * rinv; o.y = v.y * rinv; o.z = v.z * rinv; o.w = v.w * rinv;
    *(float4*)(out + ((size_t)n * KK + k) * DD + tid * 4) = o;
}

// ---------------------------------------------------------------------------
// 5) global L2 norm per n — 8 blocks per image
// ---------------------------------------------------------------------------
__global__ void __launch_bounds__(256) k_gnorm(float* __restrict__ out) {
    const int n  = blockIdx.y;
    const int sl = blockIdx.x;    // 0..7
    const int tid = threadIdx.x;
    __shared__ float red[64];
    __shared__ float rinv_s;
    if (tid < 64) red[tid] = g_nsq[n * KK + tid];
    __syncthreads();
    if (tid < 32) {
        float s = red[tid] + red[tid + 32];
#pragma unroll
        for (int m = 16; m > 0; m >>= 1)
            s += __shfl_xor_sync(0xffffffff, s, m);
        if (tid == 0) rinv_s = 1.f / fmaxf(sqrtf(s), 1e-12f);
    }
    __syncthreads();
    float rinv = rinv_s;
    float4* row = (float4*)(out + (size_t)n * KK * DD) + sl * 1024 + tid;
#pragma unroll
    for (int i = 0; i < 4; ++i) {
        float4 v = row[i * 256];
        v.x *= rinv; v.y *= rinv; v.z *= rinv; v.w *= rinv;
        row[i * 256] = v;
    }
}

// ---------------------------------------------------------------------------
extern "C" void kernel_launch(void* const* d_in, const int* in_sizes, int n_in,
                              void* d_out, int out_size) {
    const float* x = (const float*)d_in[0];        // (32, 512, 56, 56)
    const float* w = (const float*)d_in[1];        // (64, 512)
    const float* c = (const float*)d_in[2];        // (64, 512)
    float* out = (float*)d_out;                    // (32, 32768) fp32

    cudaFuncSetAttribute(k_logits_softmax,
                         cudaFuncAttributeMaxDynamicSharedMemorySize, LSM_TOTAL);
    cudaFuncSetAttribute(k_agg,
                         cudaFuncAttributeMaxDynamicSharedMemorySize, ASM_TOTAL);

    k_wbf<<<(KK * DD / 2 + 255) / 256, 256>>>(w);

    dim3 gB(NTILE, NN);                            // 25 x 32
    k_logits_softmax<<<gB, 128, LSM_TOTAL>>>(x);

    dim3 gC(DD / 128, NN, PSPLIT);                 // 4 x 32 x 7 = 896 CTAs
    k_agg<<<gC, 256, ASM_TOTAL>>>(x);

    dim3 gD(KK, NN);                               // 64 x 32
    k_vlad<<<gD, 128>>>(c, out);

    dim3 gG(8, NN);                                // 8 x 32
    k_gnorm<<<gG, 256>>>(out);
}